// round 7
// baseline (speedup 1.0000x reference)
#include <cuda_runtime.h>

#define BB 256
#define NN 256
#define KNNK 4
#define NPTS (BB*NN)

// ---------------- device scratch (allocation-free requirement) ----------------
__device__ float g_a[NPTS*192];
__device__ float g_b[NPTS*192];
__device__ float g_c[NPTS*192];
__device__ float g_d[NPTS*192];
__device__ float g_h[NPTS*192];
__device__ float g_pool[BB*768];
__device__ int   g_idx[NPTS*KNNK];

// ---------------- helpers ----------------
typedef unsigned long long ull;

__device__ __forceinline__ float leakyf(float x) { return x >= 0.f ? x : 0.01f * x; }

__device__ __forceinline__ ull pack2(float x) {
    ull r; unsigned u = __float_as_uint(x);
    asm("mov.b64 %0, {%1, %1};" : "=l"(r) : "r"(u));
    return r;
}
__device__ __forceinline__ void fma2(ull& d, ull a, ull b) {
    asm("fma.rn.f32x2 %0, %1, %2, %0;" : "+l"(d) : "l"(a), "l"(b));
}
__device__ __forceinline__ ull add2(ull a, ull b) {
    ull r;
    asm("add.rn.f32x2 %0, %1, %2;" : "=l"(r) : "l"(a), "l"(b));
    return r;
}
__device__ __forceinline__ float2 unpack2(ull v) {
    unsigned lo, hi;
    asm("mov.b64 {%0, %1}, %2;" : "=r"(lo), "=r"(hi) : "l"(v));
    return make_float2(__uint_as_float(lo), __uint_as_float(hi));
}

// ---------------- KNN: per batch, brute force 256x256, keep 4 smallest ----------------
__global__ void knn_kernel(const float* __restrict__ pos, int stride, int* __restrict__ idx) {
    __shared__ float sx[NN], sy[NN], sz[NN];
    int b = blockIdx.x, i = threadIdx.x;
    const float* p = pos + ((size_t)b * NN + i) * stride;
    sx[i] = p[0]; sy[i] = p[1]; sz[i] = p[2];
    __syncthreads();
    float xi = sx[i], yi = sy[i], zi = sz[i];
    float d0 = 1e38f, d1 = 1e38f, d2 = 1e38f, d3 = 1e38f;
    int i0 = 0, i1 = 0, i2 = 0, i3 = 0;
    for (int j = 0; j < NN; j++) {
        if (j == i) continue;
        float dx = __fadd_rn(xi, -sx[j]);
        float dy = __fadd_rn(yi, -sy[j]);
        float dz = __fadd_rn(zi, -sz[j]);
        float d = __fmaf_rn(dz, dz, __fmaf_rn(dy, dy, __fmul_rn(dx, dx)));
        if (d < d3) {
            if (d < d2) {
                d3 = d2; i3 = i2;
                if (d < d1) {
                    d2 = d1; i2 = i1;
                    if (d < d0) { d1 = d0; i1 = i0; d0 = d; i0 = j; }
                    else        { d1 = d;  i1 = j; }
                } else { d2 = d; i2 = j; }
            } else { d3 = d; i3 = j; }
        }
    }
    int base = (b * NN + i) * KNNK;
    idx[base] = i0; idx[base + 1] = i1; idx[base + 2] = i2; idx[base + 3] = i3;
}

// ---------------- vectorized-reduction GEMM core ----------------
// For a group of 8 packed pairs (16 edges): partial sum over k ≡ l (mod 8).
__device__ __forceinline__ void sweep8(ull acc[8], const float* wcol, size_t wstride,
                                       const float* smat, int g, int l, int Kmain) {
    #pragma unroll
    for (int q = 0; q < 8; q++) acc[q] = 0;
    for (int k = l; k < Kmain; k += 8) {
        ull w = pack2(wcol[(size_t)k * wstride]);
        const ulonglong2* sp = (const ulonglong2*)(smat + (size_t)k * 32) + 4 * g;
        #pragma unroll
        for (int q2 = 0; q2 < 4; q2++) {
            ulonglong2 vv = sp[q2];
            fma2(acc[2 * q2],     vv.x, w);
            fma2(acc[2 * q2 + 1], vv.y, w);
        }
    }
}
__device__ __forceinline__ void addinto8(ull a[8], const ull b[8]) {
    #pragma unroll
    for (int q = 0; q < 8; q++) a[q] = add2(a[q], b[q]);
}
// total = ((q0+q1)+(q2+q3)), q_j = p_j + p_{j+4}, p_l = sum over k≡l (mod 8),
// then sequential fma tail for k in [Kmain, K). (LLVM VF4xIC2 reduction shape.)
__device__ __forceinline__ void gemm_tree8(ull tot[8], const float* wcol, size_t wstride,
                                           const float* smat, int g, int K) {
    int Kmain = K & ~7;
    ull T[8], S[8], acc[8];
    sweep8(tot, wcol, wstride, smat, g, 0, Kmain);
    sweep8(acc, wcol, wstride, smat, g, 4, Kmain); addinto8(tot, acc);   // q0
    sweep8(T,   wcol, wstride, smat, g, 1, Kmain);
    sweep8(acc, wcol, wstride, smat, g, 5, Kmain); addinto8(T, acc);     // q1
    addinto8(tot, T);                                                    // q0+q1
    sweep8(T,   wcol, wstride, smat, g, 2, Kmain);
    sweep8(acc, wcol, wstride, smat, g, 6, Kmain); addinto8(T, acc);     // q2
    sweep8(S,   wcol, wstride, smat, g, 3, Kmain);
    sweep8(acc, wcol, wstride, smat, g, 7, Kmain); addinto8(S, acc);     // q3
    addinto8(T, S);                                                      // q2+q3
    addinto8(tot, T);
    for (int k = Kmain; k < K; k++) {                                    // scalar tail
        ull w = pack2(wcol[(size_t)k * wstride]);
        const ulonglong2* sp = (const ulonglong2*)(smat + (size_t)k * 32) + 4 * g;
        #pragma unroll
        for (int q2 = 0; q2 < 4; q2++) {
            ulonglong2 vv = sp[q2];
            fma2(tot[2 * q2],     vv.x, w);
            fma2(tot[2 * q2 + 1], vv.y, w);
        }
    }
}

// ---------------- fused EdgeConv (vectorized-reduction order) ----------------
// 8 points (32 edges) per block, blockDim=256, dynamic smem.
__global__ void edgeconv_kernel(const float* __restrict__ feat, int Fin, int H,
                                const int* __restrict__ idx,
                                const float* __restrict__ w1, const float* __restrict__ b1,
                                const float* __restrict__ w2, const float* __restrict__ b2,
                                float* __restrict__ out) {
    extern __shared__ float smem_[];
    const int Cout = 192;
    int F2 = 2 * Fin;
    float* sf = smem_;                    // [k*32 + e], k in [0,F2)
    float* s  = smem_ + (size_t)F2 * 32;  // [j*32 + e], j in [0,H)
    int*   nb = (int*)(s + 252 * 32);     // [32]

    int m0 = blockIdx.x * 8;
    int tid = threadIdx.x;

    if (tid < 32) {
        int p = tid >> 2;
        int m = m0 + p;
        nb[tid] = (m & ~(NN - 1)) + idx[m * KNNK + (tid & 3)];
    }
    __syncthreads();

    for (int t = tid; t < F2 * 32; t += 256) {
        int e = t & 31, k = t >> 5;
        int p = e >> 2;
        float v;
        if (k < Fin) {
            v = feat[(size_t)(m0 + p) * Fin + k];
        } else {
            int kk = k - Fin;
            v = __fadd_rn(feat[(size_t)nb[e] * Fin + kk], -feat[(size_t)(m0 + p) * Fin + kk]);
        }
        sf[t] = v;
    }
    __syncthreads();

    // GEMM 1: s = leaky(e @ w1 + b1)
    if (tid < H) {
        int j = tid;
        float bb = b1[j];
        #pragma unroll
        for (int g = 0; g < 2; g++) {
            ull tot[8];
            gemm_tree8(tot, w1 + j, H, sf, g, F2);
            #pragma unroll
            for (int q = 0; q < 8; q++) {
                float2 r = unpack2(tot[q]);
                int e0 = 16 * g + 2 * q;
                s[j * 32 + e0]     = leakyf(__fadd_rn(r.x, bb));
                s[j * 32 + e0 + 1] = leakyf(__fadd_rn(r.y, bb));
            }
        }
    }
    __syncthreads();

    // GEMM 2 + leaky + sum over the 4 edges of each point
    if (tid < Cout) {
        int o = tid;
        float bb = b2[o];
        #pragma unroll
        for (int g = 0; g < 2; g++) {
            ull tot[8];
            gemm_tree8(tot, w2 + o, Cout, s, g, H);
            #pragma unroll
            for (int pp = 0; pp < 4; pp++) {
                float2 x0 = unpack2(tot[2 * pp]);      // edges k=0,1 of point
                float2 x1 = unpack2(tot[2 * pp + 1]);  // edges k=2,3
                float r = leakyf(x0.x + bb) + leakyf(x0.y + bb) +
                          leakyf(x1.x + bb) + leakyf(x1.y + bb);
                out[(size_t)(m0 + 4 * g + pp) * Cout + o] = r;
            }
        }
    }
}

// ---------------- nn1+nn2 fused per point (unchanged: value-noise only) ----------------
__global__ void nn12_kernel(const float* __restrict__ x,
                            const float* __restrict__ a, const float* __restrict__ b,
                            const float* __restrict__ c, const float* __restrict__ d,
                            const float* __restrict__ w1, const float* __restrict__ b1,
                            const float* __restrict__ w2, const float* __restrict__ b2,
                            float* __restrict__ hout) {
    __shared__ __align__(16) float sin_[772 * 8];
    __shared__ __align__(16) float sh1[252 * 8];
    int m0 = blockIdx.x * 8;
    int tid = threadIdx.x;
    for (int e = tid; e < 772 * 8; e += blockDim.x) {
        int ch = e >> 3, p = e & 7;
        size_t mp = (size_t)(m0 + p);
        float val;
        if (ch < 4)        val = x[mp * 4 + ch];
        else if (ch < 196) val = a[mp * 192 + (ch - 4)];
        else if (ch < 388) val = b[mp * 192 + (ch - 196)];
        else if (ch < 580) val = c[mp * 192 + (ch - 388)];
        else               val = d[mp * 192 + (ch - 580)];
        sin_[e] = val;
    }
    __syncthreads();
    if (tid < 252) {
        int j = tid;
        ull acc[4] = {0, 0, 0, 0};
        for (int k = 0; k < 772; k++) {
            ull wp = pack2(w1[(size_t)k * 252 + j]);
            const ulonglong2* sp = (const ulonglong2*)&sin_[k * 8];
            ulonglong2 s0 = sp[0], s1 = sp[1];
            fma2(acc[0], s0.x, wp); fma2(acc[1], s0.y, wp);
            fma2(acc[2], s1.x, wp); fma2(acc[3], s1.y, wp);
        }
        float bb = b1[j];
        #pragma unroll
        for (int q = 0; q < 4; q++) {
            float2 r2 = unpack2(acc[q]);
            sh1[j * 8 + q * 2]     = leakyf(r2.x + bb);
            sh1[j * 8 + q * 2 + 1] = leakyf(r2.y + bb);
        }
    }
    __syncthreads();
    if (tid < 192) {
        int o = tid;
        ull acc[4] = {0, 0, 0, 0};
        for (int mm = 0; mm < 252; mm++) {
            ull wp = pack2(w2[mm * 192 + o]);
            const ulonglong2* sp = (const ulonglong2*)&sh1[mm * 8];
            ulonglong2 s0 = sp[0], s1 = sp[1];
            fma2(acc[0], s0.x, wp); fma2(acc[1], s0.y, wp);
            fma2(acc[2], s1.x, wp); fma2(acc[3], s1.y, wp);
        }
        float bb = b2[o];
        #pragma unroll
        for (int q = 0; q < 4; q++) {
            float2 r2 = unpack2(acc[q]);
            hout[(size_t)(m0 + q * 2) * 192 + o]     = r2.x + bb;
            hout[(size_t)(m0 + q * 2 + 1) * 192 + o] = r2.y + bb;
        }
    }
}

// ---------------- pooling (fp64 sum, R6 form) ----------------
__global__ void pool_kernel(const float* __restrict__ h, float* __restrict__ pooled) {
    int b = blockIdx.x, cch = threadIdx.x;
    const float* hp = h + (size_t)b * NN * 192 + cch;
    float mx = -1e38f, mn = 1e38f;
    double sm = 0.0;
    for (int n = 0; n < NN; n++) {
        float v = hp[(size_t)n * 192];
        mx = fmaxf(mx, v); mn = fminf(mn, v);
        sm += (double)v;
    }
    float smf = (float)sm;
    float* pb = pooled + b * 768;
    pb[cch]       = leakyf(mx);
    pb[192 + cch] = leakyf(mn);
    pb[384 + cch] = leakyf(smf);
    pb[576 + cch] = leakyf(__fmul_rn(smf, (1.0f / 256.0f)));
}

// ---------------- final head ----------------
__global__ void final_kernel(const float* __restrict__ pooled,
                             const float* __restrict__ w3, const float* __restrict__ b3,
                             const float* __restrict__ w4, const float* __restrict__ b4,
                             float* __restrict__ out) {
    __shared__ float sp[768];
    __shared__ float smid[96];
    int b = blockIdx.x, tid = threadIdx.x;
    for (int e = tid; e < 768; e += blockDim.x) sp[e] = pooled[b * 768 + e];
    __syncthreads();
    if (tid < 96) {
        float acc = 0.f;
        for (int k = 0; k < 768; k++) acc = fmaf(sp[k], w3[k * 96 + tid], acc);
        smid[tid] = leakyf(acc + b3[tid]);
    }
    __syncthreads();
    if (tid == 0) {
        float sacc = 0.f;
        for (int k = 0; k < 96; k++) sacc = fmaf(smid[k], w4[k], sacc);
        out[b] = sacc + b4[0];
    }
}

// ---------------- launch ----------------
extern "C" void kernel_launch(void* const* d_in, const int* in_sizes, int n_in,
                              void* d_out, int out_size) {
    const float* x = (const float*)d_in[0];
    const float* prm[24];
    for (int i = 0; i < 24; i++) prm[i] = (const float*)d_in[i + 1];

    float *ga, *gb, *gc, *gd, *gh, *gp;
    int* gi;
    cudaGetSymbolAddress((void**)&ga, g_a);
    cudaGetSymbolAddress((void**)&gb, g_b);
    cudaGetSymbolAddress((void**)&gc, g_c);
    cudaGetSymbolAddress((void**)&gd, g_d);
    cudaGetSymbolAddress((void**)&gh, g_h);
    cudaGetSymbolAddress((void**)&gp, g_pool);
    cudaGetSymbolAddress((void**)&gi, g_idx);

    int smem1 = (8   * 32 + 252 * 32) * 4 + 32 * 4;
    int smem2 = (384 * 32 + 252 * 32) * 4 + 32 * 4;
    cudaFuncSetAttribute(edgeconv_kernel, cudaFuncAttributeMaxDynamicSharedMemorySize, smem2);

    knn_kernel<<<BB, NN>>>(x, 4, gi);
    edgeconv_kernel<<<NPTS / 8, 256, smem1>>>(x, 4, 96, gi, prm[0], prm[1], prm[2], prm[3], ga);

    knn_kernel<<<BB, NN>>>(ga, 192, gi);
    edgeconv_kernel<<<NPTS / 8, 256, smem2>>>(ga, 192, 252, gi, prm[4], prm[5], prm[6], prm[7], gb);

    knn_kernel<<<BB, NN>>>(gb, 192, gi);
    edgeconv_kernel<<<NPTS / 8, 256, smem2>>>(gb, 192, 252, gi, prm[8], prm[9], prm[10], prm[11], gc);

    knn_kernel<<<BB, NN>>>(gc, 192, gi);
    edgeconv_kernel<<<NPTS / 8, 256, smem2>>>(gc, 192, 252, gi, prm[12], prm[13], prm[14], prm[15], gd);

    nn12_kernel<<<NPTS / 8, 256>>>(x, ga, gb, gc, gd,
                                   prm[16], prm[17], prm[18], prm[19], gh);

    pool_kernel<<<BB, 192>>>(gh, gp);
    final_kernel<<<BB, 128>>>(gp, prm[20], prm[21], prm[22], prm[23], (float*)d_out);
}

// round 8
// speedup vs baseline: 1.5277x; 1.5277x over previous
#include <cuda_runtime.h>

#define BB 256
#define NN 256
#define KNNK 4
#define NPTS (BB*NN)

// ---------------- device scratch (allocation-free requirement) ----------------
__device__ float g_a[NPTS*192];
__device__ float g_b[NPTS*192];
__device__ float g_c[NPTS*192];
__device__ float g_d[NPTS*192];
__device__ float g_h[NPTS*192];
__device__ float g_pool[BB*768];
__device__ int   g_idx[NPTS*KNNK];

// ---------------- helpers ----------------
typedef unsigned long long ull;

__device__ __forceinline__ float leakyf(float x) { return x >= 0.f ? x : 0.01f * x; }

__device__ __forceinline__ ull pack2(float x) {
    ull r; unsigned u = __float_as_uint(x);
    asm("mov.b64 %0, {%1, %1};" : "=l"(r) : "r"(u));
    return r;
}
__device__ __forceinline__ void fma2(ull& d, ull a, ull b) {
    asm("fma.rn.f32x2 %0, %1, %2, %0;" : "+l"(d) : "l"(a), "l"(b));
}
__device__ __forceinline__ ull add2(ull a, ull b) {
    ull r;
    asm("add.rn.f32x2 %0, %1, %2;" : "=l"(r) : "l"(a), "l"(b));
    return r;
}
__device__ __forceinline__ float2 unpack2(ull v) {
    unsigned lo, hi;
    asm("mov.b64 {%0, %1}, %2;" : "=r"(lo), "=r"(hi) : "l"(v));
    return make_float2(__uint_as_float(lo), __uint_as_float(hi));
}

// ---------------- KNN (unchanged from R7) ----------------
__global__ void knn_kernel(const float* __restrict__ pos, int stride, int* __restrict__ idx) {
    __shared__ float sx[NN], sy[NN], sz[NN];
    int b = blockIdx.x, i = threadIdx.x;
    const float* p = pos + ((size_t)b * NN + i) * stride;
    sx[i] = p[0]; sy[i] = p[1]; sz[i] = p[2];
    __syncthreads();
    float xi = sx[i], yi = sy[i], zi = sz[i];
    float d0 = 1e38f, d1 = 1e38f, d2 = 1e38f, d3 = 1e38f;
    int i0 = 0, i1 = 0, i2 = 0, i3 = 0;
    for (int j = 0; j < NN; j++) {
        if (j == i) continue;
        float dx = __fadd_rn(xi, -sx[j]);
        float dy = __fadd_rn(yi, -sy[j]);
        float dz = __fadd_rn(zi, -sz[j]);
        float d = __fmaf_rn(dz, dz, __fmaf_rn(dy, dy, __fmul_rn(dx, dx)));
        if (d < d3) {
            if (d < d2) {
                d3 = d2; i3 = i2;
                if (d < d1) {
                    d2 = d1; i2 = i1;
                    if (d < d0) { d1 = d0; i1 = i0; d0 = d; i0 = j; }
                    else        { d1 = d;  i1 = j; }
                } else { d2 = d; i2 = j; }
            } else { d3 = d; i3 = j; }
        }
    }
    int base = (b * NN + i) * KNNK;
    idx[base] = i0; idx[base + 1] = i1; idx[base + 2] = i2; idx[base + 3] = i3;
}

// ---------------- vectorized-reduction GEMM core (4-pair / 8-edge slice) ----------------
// Per-lane math identical to R7's tree8: p_l = sum over k≡l (mod 8),
// q_j = p_j + p_{j+4}, total = ((q0+q1)+(q2+q3)), then sequential tail.
// smat = this thread's 8-edge slice base; row stride = rowstride floats.
__device__ __forceinline__ void sweep4(ull acc[4], const float* __restrict__ wcol, int wstride,
                                       const float* __restrict__ smat, int rowstride,
                                       int l, int Kmain) {
    #pragma unroll
    for (int q = 0; q < 4; q++) acc[q] = 0;
    for (int k = l; k < Kmain; k += 8) {
        ull w = pack2(wcol[(size_t)k * wstride]);
        const ulonglong2* sp = (const ulonglong2*)(smat + (size_t)k * rowstride);
        ulonglong2 v0 = sp[0], v1 = sp[1];
        fma2(acc[0], v0.x, w); fma2(acc[1], v0.y, w);
        fma2(acc[2], v1.x, w); fma2(acc[3], v1.y, w);
    }
}
__device__ __forceinline__ void addinto4(ull a[4], const ull b[4]) {
    #pragma unroll
    for (int q = 0; q < 4; q++) a[q] = add2(a[q], b[q]);
}
__device__ __forceinline__ void gemm_tree4(ull tot[4], const float* __restrict__ wcol, int wstride,
                                           const float* __restrict__ smat, int rowstride, int K) {
    int Kmain = K & ~7;
    ull T[4], S[4], acc[4];
    sweep4(tot, wcol, wstride, smat, rowstride, 0, Kmain);
    sweep4(acc, wcol, wstride, smat, rowstride, 4, Kmain); addinto4(tot, acc);  // q0
    sweep4(T,   wcol, wstride, smat, rowstride, 1, Kmain);
    sweep4(acc, wcol, wstride, smat, rowstride, 5, Kmain); addinto4(T, acc);    // q1
    addinto4(tot, T);                                                           // q0+q1
    sweep4(T,   wcol, wstride, smat, rowstride, 2, Kmain);
    sweep4(acc, wcol, wstride, smat, rowstride, 6, Kmain); addinto4(T, acc);    // q2
    sweep4(S,   wcol, wstride, smat, rowstride, 3, Kmain);
    sweep4(acc, wcol, wstride, smat, rowstride, 7, Kmain); addinto4(S, acc);    // q3
    addinto4(T, S);                                                             // q2+q3
    addinto4(tot, T);
    for (int k = Kmain; k < K; k++) {                                           // scalar tail
        ull w = pack2(wcol[(size_t)k * wstride]);
        const ulonglong2* sp = (const ulonglong2*)(smat + (size_t)k * rowstride);
        ulonglong2 v0 = sp[0], v1 = sp[1];
        fma2(tot[0], v0.x, w); fma2(tot[1], v0.y, w);
        fma2(tot[2], v1.x, w); fma2(tot[3], v1.y, w);
    }
}

// ---------------- fused EdgeConv: 4 points (16 edges) per block, 512 threads ----------------
// thread = (channel, half h): half h owns edges [8h, 8h+8) = packed pairs [4h, 4h+4).
// Per-lane accumulation order identical to R7 (lane = edge; partitioning is order-free).
__global__ void __launch_bounds__(512, 2)
edgeconv_kernel(const float* __restrict__ feat, int Fin, int H,
                const int* __restrict__ idx,
                const float* __restrict__ w1, const float* __restrict__ b1,
                const float* __restrict__ w2, const float* __restrict__ b2,
                float* __restrict__ out) {
    extern __shared__ float smem_[];
    const int Cout = 192;
    int F2 = 2 * Fin;
    float* sf = smem_;                    // [k*16 + e], k in [0,F2)
    float* s  = smem_ + (size_t)F2 * 16;  // [j*16 + e], j in [0,H)
    int*   nb = (int*)(s + 252 * 16);     // [16]

    int m0 = blockIdx.x * 4;
    int tid = threadIdx.x;

    if (tid < 16) {
        int p = tid >> 2;
        int m = m0 + p;
        nb[tid] = (m & ~(NN - 1)) + idx[m * KNNK + (tid & 3)];
    }
    __syncthreads();

    // build edge features: e = [xi, rn(xj - xi)]
    for (int t = tid; t < F2 * 16; t += 512) {
        int e = t & 15, k = t >> 4;
        int p = e >> 2;
        float v;
        if (k < Fin) {
            v = feat[(size_t)(m0 + p) * Fin + k];
        } else {
            int kk = k - Fin;
            v = __fadd_rn(feat[(size_t)nb[e] * Fin + kk], -feat[(size_t)(m0 + p) * Fin + kk]);
        }
        sf[t] = v;
    }
    __syncthreads();

    // GEMM 1: s = leaky(e @ w1 + b1); thread (j = tid>>1, h = tid&1)
    {
        int j = tid >> 1, h = tid & 1;
        if (j < H) {
            ull tot[4];
            gemm_tree4(tot, w1 + j, H, sf + 8 * h, 16, F2);
            float bb = b1[j];
            #pragma unroll
            for (int q = 0; q < 4; q++) {
                float2 r = unpack2(tot[q]);
                int e0 = 8 * h + 2 * q;
                s[j * 16 + e0]     = leakyf(__fadd_rn(r.x, bb));
                s[j * 16 + e0 + 1] = leakyf(__fadd_rn(r.y, bb));
            }
        }
    }
    __syncthreads();

    // GEMM 2 + leaky + sum over the 4 edges of each point; thread (o = tid>>1, h = tid&1)
    {
        int o = tid >> 1, h = tid & 1;
        if (o < Cout) {
            ull tot[4];
            gemm_tree4(tot, w2 + o, Cout, s + 8 * h, 16, H);
            float bb = b2[o];
            #pragma unroll
            for (int pp = 0; pp < 2; pp++) {   // points 2h, 2h+1
                float2 x0 = unpack2(tot[2 * pp]);      // edges 0,1 of the point
                float2 x1 = unpack2(tot[2 * pp + 1]);  // edges 2,3
                float r = leakyf(x0.x + bb) + leakyf(x0.y + bb) +
                          leakyf(x1.x + bb) + leakyf(x1.y + bb);
                out[(size_t)(m0 + 2 * h + pp) * Cout + o] = r;
            }
        }
    }
}

// ---------------- nn1+nn2 fused per point (unchanged from R7) ----------------
__global__ void nn12_kernel(const float* __restrict__ x,
                            const float* __restrict__ a, const float* __restrict__ b,
                            const float* __restrict__ c, const float* __restrict__ d,
                            const float* __restrict__ w1, const float* __restrict__ b1,
                            const float* __restrict__ w2, const float* __restrict__ b2,
                            float* __restrict__ hout) {
    __shared__ __align__(16) float sin_[772 * 8];
    __shared__ __align__(16) float sh1[252 * 8];
    int m0 = blockIdx.x * 8;
    int tid = threadIdx.x;
    for (int e = tid; e < 772 * 8; e += blockDim.x) {
        int ch = e >> 3, p = e & 7;
        size_t mp = (size_t)(m0 + p);
        float val;
        if (ch < 4)        val = x[mp * 4 + ch];
        else if (ch < 196) val = a[mp * 192 + (ch - 4)];
        else if (ch < 388) val = b[mp * 192 + (ch - 196)];
        else if (ch < 580) val = c[mp * 192 + (ch - 388)];
        else               val = d[mp * 192 + (ch - 580)];
        sin_[e] = val;
    }
    __syncthreads();
    if (tid < 252) {
        int j = tid;
        ull acc[4] = {0, 0, 0, 0};
        for (int k = 0; k < 772; k++) {
            ull wp = pack2(w1[(size_t)k * 252 + j]);
            const ulonglong2* sp = (const ulonglong2*)&sin_[k * 8];
            ulonglong2 s0 = sp[0], s1 = sp[1];
            fma2(acc[0], s0.x, wp); fma2(acc[1], s0.y, wp);
            fma2(acc[2], s1.x, wp); fma2(acc[3], s1.y, wp);
        }
        float bb = b1[j];
        #pragma unroll
        for (int q = 0; q < 4; q++) {
            float2 r2 = unpack2(acc[q]);
            sh1[j * 8 + q * 2]     = leakyf(r2.x + bb);
            sh1[j * 8 + q * 2 + 1] = leakyf(r2.y + bb);
        }
    }
    __syncthreads();
    if (tid < 192) {
        int o = tid;
        ull acc[4] = {0, 0, 0, 0};
        for (int mm = 0; mm < 252; mm++) {
            ull wp = pack2(w2[mm * 192 + o]);
            const ulonglong2* sp = (const ulonglong2*)&sh1[mm * 8];
            ulonglong2 s0 = sp[0], s1 = sp[1];
            fma2(acc[0], s0.x, wp); fma2(acc[1], s0.y, wp);
            fma2(acc[2], s1.x, wp); fma2(acc[3], s1.y, wp);
        }
        float bb = b2[o];
        #pragma unroll
        for (int q = 0; q < 4; q++) {
            float2 r2 = unpack2(acc[q]);
            hout[(size_t)(m0 + q * 2) * 192 + o]     = r2.x + bb;
            hout[(size_t)(m0 + q * 2 + 1) * 192 + o] = r2.y + bb;
        }
    }
}

// ---------------- pooling (unchanged from R7) ----------------
__global__ void pool_kernel(const float* __restrict__ h, float* __restrict__ pooled) {
    int b = blockIdx.x, cch = threadIdx.x;
    const float* hp = h + (size_t)b * NN * 192 + cch;
    float mx = -1e38f, mn = 1e38f;
    double sm = 0.0;
    for (int n = 0; n < NN; n++) {
        float v = hp[(size_t)n * 192];
        mx = fmaxf(mx, v); mn = fminf(mn, v);
        sm += (double)v;
    }
    float smf = (float)sm;
    float* pb = pooled + b * 768;
    pb[cch]       = leakyf(mx);
    pb[192 + cch] = leakyf(mn);
    pb[384 + cch] = leakyf(smf);
    pb[576 + cch] = leakyf(__fmul_rn(smf, (1.0f / 256.0f)));
}

// ---------------- final head (unchanged from R7) ----------------
__global__ void final_kernel(const float* __restrict__ pooled,
                             const float* __restrict__ w3, const float* __restrict__ b3,
                             const float* __restrict__ w4, const float* __restrict__ b4,
                             float* __restrict__ out) {
    __shared__ float sp[768];
    __shared__ float smid[96];
    int b = blockIdx.x, tid = threadIdx.x;
    for (int e = tid; e < 768; e += blockDim.x) sp[e] = pooled[b * 768 + e];
    __syncthreads();
    if (tid < 96) {
        float acc = 0.f;
        for (int k = 0; k < 768; k++) acc = fmaf(sp[k], w3[k * 96 + tid], acc);
        smid[tid] = leakyf(acc + b3[tid]);
    }
    __syncthreads();
    if (tid == 0) {
        float sacc = 0.f;
        for (int k = 0; k < 96; k++) sacc = fmaf(smid[k], w4[k], sacc);
        out[b] = sacc + b4[0];
    }
}

// ---------------- launch ----------------
extern "C" void kernel_launch(void* const* d_in, const int* in_sizes, int n_in,
                              void* d_out, int out_size) {
    const float* x = (const float*)d_in[0];
    const float* prm[24];
    for (int i = 0; i < 24; i++) prm[i] = (const float*)d_in[i + 1];

    float *ga, *gb, *gc, *gd, *gh, *gp;
    int* gi;
    cudaGetSymbolAddress((void**)&ga, g_a);
    cudaGetSymbolAddress((void**)&gb, g_b);
    cudaGetSymbolAddress((void**)&gc, g_c);
    cudaGetSymbolAddress((void**)&gd, g_d);
    cudaGetSymbolAddress((void**)&gh, g_h);
    cudaGetSymbolAddress((void**)&gp, g_pool);
    cudaGetSymbolAddress((void**)&gi, g_idx);

    // dynamic smem: (F2*16 + 252*16) floats + 16 ints
    int smem1 = (8   * 16 + 252 * 16) * 4 + 16 * 4;   // conv1 (Fin=4)   ~16.7KB
    int smem2 = (384 * 16 + 252 * 16) * 4 + 16 * 4;   // convs 2-4       ~40.8KB
    cudaFuncSetAttribute(edgeconv_kernel, cudaFuncAttributeMaxDynamicSharedMemorySize, smem2);

    knn_kernel<<<BB, NN>>>(x, 4, gi);
    edgeconv_kernel<<<NPTS / 4, 512, smem1>>>(x, 4, 96, gi, prm[0], prm[1], prm[2], prm[3], ga);

    knn_kernel<<<BB, NN>>>(ga, 192, gi);
    edgeconv_kernel<<<NPTS / 4, 512, smem2>>>(ga, 192, 252, gi, prm[4], prm[5], prm[6], prm[7], gb);

    knn_kernel<<<BB, NN>>>(gb, 192, gi);
    edgeconv_kernel<<<NPTS / 4, 512, smem2>>>(gb, 192, 252, gi, prm[8], prm[9], prm[10], prm[11], gc);

    knn_kernel<<<BB, NN>>>(gc, 192, gi);
    edgeconv_kernel<<<NPTS / 4, 512, smem2>>>(gc, 192, 252, gi, prm[12], prm[13], prm[14], prm[15], gd);

    nn12_kernel<<<NPTS / 8, 256>>>(x, ga, gb, gc, gd,
                                   prm[16], prm[17], prm[18], prm[19], gh);

    pool_kernel<<<BB, 192>>>(gh, gp);
    final_kernel<<<BB, 128>>>(gp, prm[20], prm[21], prm[22], prm[23], (float*)d_out);
}

// round 9
// speedup vs baseline: 1.6012x; 1.0482x over previous
#include <cuda_runtime.h>

#define BB 256
#define NN 256
#define KNNK 4
#define NPTS (BB*NN)

// ---------------- device scratch (allocation-free requirement) ----------------
__device__ float g_a[NPTS*192];
__device__ float g_b[NPTS*192];
__device__ float g_c[NPTS*192];
__device__ float g_d[NPTS*192];
__device__ float g_h[NPTS*192];
__device__ float g_pool[BB*768];
__device__ int   g_idx[NPTS*KNNK];

// ---------------- helpers ----------------
typedef unsigned long long ull;

__device__ __forceinline__ float leakyf(float x) { return x >= 0.f ? x : 0.01f * x; }

__device__ __forceinline__ ull pack2(float x) {
    ull r; unsigned u = __float_as_uint(x);
    asm("mov.b64 %0, {%1, %1};" : "=l"(r) : "r"(u));
    return r;
}
__device__ __forceinline__ void fma2(ull& d, ull a, ull b) {
    asm("fma.rn.f32x2 %0, %1, %2, %0;" : "+l"(d) : "l"(a), "l"(b));
}
__device__ __forceinline__ ull add2(ull a, ull b) {
    ull r;
    asm("add.rn.f32x2 %0, %1, %2;" : "=l"(r) : "l"(a), "l"(b));
    return r;
}
__device__ __forceinline__ float2 unpack2(ull v) {
    unsigned lo, hi;
    asm("mov.b64 {%0, %1}, %2;" : "=r"(lo), "=r"(hi) : "l"(v));
    return make_float2(__uint_as_float(lo), __uint_as_float(hi));
}

// ---------------- KNN (unchanged) ----------------
__global__ void knn_kernel(const float* __restrict__ pos, int stride, int* __restrict__ idx) {
    __shared__ float sx[NN], sy[NN], sz[NN];
    int b = blockIdx.x, i = threadIdx.x;
    const float* p = pos + ((size_t)b * NN + i) * stride;
    sx[i] = p[0]; sy[i] = p[1]; sz[i] = p[2];
    __syncthreads();
    float xi = sx[i], yi = sy[i], zi = sz[i];
    float d0 = 1e38f, d1 = 1e38f, d2 = 1e38f, d3 = 1e38f;
    int i0 = 0, i1 = 0, i2 = 0, i3 = 0;
    for (int j = 0; j < NN; j++) {
        if (j == i) continue;
        float dx = __fadd_rn(xi, -sx[j]);
        float dy = __fadd_rn(yi, -sy[j]);
        float dz = __fadd_rn(zi, -sz[j]);
        float d = __fmaf_rn(dz, dz, __fmaf_rn(dy, dy, __fmul_rn(dx, dx)));
        if (d < d3) {
            if (d < d2) {
                d3 = d2; i3 = i2;
                if (d < d1) {
                    d2 = d1; i2 = i1;
                    if (d < d0) { d1 = d0; i1 = i0; d0 = d; i0 = j; }
                    else        { d1 = d;  i1 = j; }
                } else { d2 = d; i2 = j; }
            } else { d3 = d; i3 = j; }
        }
    }
    int base = (b * NN + i) * KNNK;
    idx[base] = i0; idx[base + 1] = i1; idx[base + 2] = i2; idx[base + 3] = i3;
}

// ---------------- vectorized-reduction GEMM core, compile-time K ----------------
// Per-lane math identical to R7/R8: p_l = sum over k≡l (mod 8),
// q_j = p_j + p_{j+4}, total = ((q0+q1)+(q2+q3)), sequential tail.
template<int K, int L>
__device__ __forceinline__ void sweepT(ull acc[4], const float* __restrict__ wcol, int wstride,
                                       const float* __restrict__ smat) {
    #pragma unroll
    for (int q = 0; q < 4; q++) acc[q] = 0;
    constexpr int KMAIN = K & ~7;
    #pragma unroll 4
    for (int k = L; k < KMAIN; k += 8) {
        ull w = pack2(__ldg(wcol + (size_t)k * wstride));
        const ulonglong2* sp = (const ulonglong2*)(smat + k * 16);
        ulonglong2 v0 = sp[0], v1 = sp[1];
        fma2(acc[0], v0.x, w); fma2(acc[1], v0.y, w);
        fma2(acc[2], v1.x, w); fma2(acc[3], v1.y, w);
    }
}
__device__ __forceinline__ void addinto4(ull a[4], const ull b[4]) {
    #pragma unroll
    for (int q = 0; q < 4; q++) a[q] = add2(a[q], b[q]);
}
template<int K>
__device__ __forceinline__ void gemm_tree4T(ull tot[4], const float* __restrict__ wcol, int wstride,
                                            const float* __restrict__ smat) {
    ull T[4], S[4], acc[4];
    sweepT<K, 0>(tot, wcol, wstride, smat);
    sweepT<K, 4>(acc, wcol, wstride, smat); addinto4(tot, acc);  // q0
    sweepT<K, 1>(T,   wcol, wstride, smat);
    sweepT<K, 5>(acc, wcol, wstride, smat); addinto4(T, acc);    // q1
    addinto4(tot, T);                                            // q0+q1
    sweepT<K, 2>(T,   wcol, wstride, smat);
    sweepT<K, 6>(acc, wcol, wstride, smat); addinto4(T, acc);    // q2
    sweepT<K, 3>(S,   wcol, wstride, smat);
    sweepT<K, 7>(acc, wcol, wstride, smat); addinto4(S, acc);    // q3
    addinto4(T, S);                                              // q2+q3
    addinto4(tot, T);
    constexpr int KMAIN = K & ~7;
    #pragma unroll
    for (int k = KMAIN; k < K; k++) {                            // scalar tail
        ull w = pack2(__ldg(wcol + (size_t)k * wstride));
        const ulonglong2* sp = (const ulonglong2*)(smat + k * 16);
        ulonglong2 v0 = sp[0], v1 = sp[1];
        fma2(tot[0], v0.x, w); fma2(tot[1], v0.y, w);
        fma2(tot[2], v1.x, w); fma2(tot[3], v1.y, w);
    }
}

// ---------------- fused EdgeConv: 4 points (16 edges)/block, 512 threads ----------------
// thread = (channel, half h); per-lane accumulation order identical to R8.
template<int FIN, int H>
__global__ void __launch_bounds__(512, 2)
edgeconv_kernel(const float* __restrict__ feat,
                const int* __restrict__ idx,
                const float* __restrict__ w1, const float* __restrict__ b1,
                const float* __restrict__ w2, const float* __restrict__ b2,
                float* __restrict__ out) {
    constexpr int Cout = 192;
    constexpr int F2 = 2 * FIN;
    __shared__ __align__(16) float sf[F2 * 16];   // [k*16 + e]
    __shared__ __align__(16) float s[252 * 16];   // [j*16 + e] (H<=252)
    __shared__ int nb[16];

    int m0 = blockIdx.x * 4;
    int tid = threadIdx.x;

    if (tid < 16) {
        int p = tid >> 2;
        int m = m0 + p;
        nb[tid] = (m & ~(NN - 1)) + idx[m * KNNK + (tid & 3)];
    }
    __syncthreads();

    // build edge features: e = [xi, rn(xj - xi)]
    #pragma unroll 2
    for (int t = tid; t < F2 * 16; t += 512) {
        int e = t & 15, k = t >> 4;
        int p = e >> 2;
        float v;
        if (k < FIN) {
            v = feat[(size_t)(m0 + p) * FIN + k];
        } else {
            int kk = k - FIN;
            v = __fadd_rn(feat[(size_t)nb[e] * FIN + kk], -feat[(size_t)(m0 + p) * FIN + kk]);
        }
        sf[t] = v;
    }
    __syncthreads();

    // GEMM 1: s = leaky(e @ w1 + b1); thread (j = tid>>1, h = tid&1)
    {
        int j = tid >> 1, h = tid & 1;
        if (j < H) {
            ull tot[4];
            gemm_tree4T<F2>(tot, w1 + j, H, sf + 8 * h);
            float bb = b1[j];
            #pragma unroll
            for (int q = 0; q < 4; q++) {
                float2 r = unpack2(tot[q]);
                int e0 = 8 * h + 2 * q;
                s[j * 16 + e0]     = leakyf(__fadd_rn(r.x, bb));
                s[j * 16 + e0 + 1] = leakyf(__fadd_rn(r.y, bb));
            }
        }
    }
    __syncthreads();

    // GEMM 2 + leaky + sum over the 4 edges of each point; thread (o = tid>>1, h = tid&1)
    {
        int o = tid >> 1, h = tid & 1;
        if (o < Cout) {
            ull tot[4];
            gemm_tree4T<H>(tot, w2 + o, Cout, s + 8 * h);
            float bb = b2[o];
            #pragma unroll
            for (int pp = 0; pp < 2; pp++) {   // points 2h, 2h+1
                float2 x0 = unpack2(tot[2 * pp]);
                float2 x1 = unpack2(tot[2 * pp + 1]);
                float r = leakyf(x0.x + bb) + leakyf(x0.y + bb) +
                          leakyf(x1.x + bb) + leakyf(x1.y + bb);
                out[(size_t)(m0 + 2 * h + pp) * Cout + o] = r;
            }
        }
    }
}

// ---------------- nn1+nn2 fused per point (k-loops unrolled; same order) ----------------
__global__ void nn12_kernel(const float* __restrict__ x,
                            const float* __restrict__ a, const float* __restrict__ b,
                            const float* __restrict__ c, const float* __restrict__ d,
                            const float* __restrict__ w1, const float* __restrict__ b1,
                            const float* __restrict__ w2, const float* __restrict__ b2,
                            float* __restrict__ hout) {
    __shared__ __align__(16) float sin_[772 * 8];
    __shared__ __align__(16) float sh1[252 * 8];
    int m0 = blockIdx.x * 8;
    int tid = threadIdx.x;
    for (int e = tid; e < 772 * 8; e += blockDim.x) {
        int ch = e >> 3, p = e & 7;
        size_t mp = (size_t)(m0 + p);
        float val;
        if (ch < 4)        val = x[mp * 4 + ch];
        else if (ch < 196) val = a[mp * 192 + (ch - 4)];
        else if (ch < 388) val = b[mp * 192 + (ch - 196)];
        else if (ch < 580) val = c[mp * 192 + (ch - 388)];
        else               val = d[mp * 192 + (ch - 580)];
        sin_[e] = val;
    }
    __syncthreads();
    if (tid < 252) {
        int j = tid;
        ull acc[4] = {0, 0, 0, 0};
        #pragma unroll 4
        for (int k = 0; k < 772; k++) {
            ull wp = pack2(__ldg(w1 + (size_t)k * 252 + j));
            const ulonglong2* sp = (const ulonglong2*)&sin_[k * 8];
            ulonglong2 s0 = sp[0], s1 = sp[1];
            fma2(acc[0], s0.x, wp); fma2(acc[1], s0.y, wp);
            fma2(acc[2], s1.x, wp); fma2(acc[3], s1.y, wp);
        }
        float bb = b1[j];
        #pragma unroll
        for (int q = 0; q < 4; q++) {
            float2 r2 = unpack2(acc[q]);
            sh1[j * 8 + q * 2]     = leakyf(r2.x + bb);
            sh1[j * 8 + q * 2 + 1] = leakyf(r2.y + bb);
        }
    }
    __syncthreads();
    if (tid < 192) {
        int o = tid;
        ull acc[4] = {0, 0, 0, 0};
        #pragma unroll 4
        for (int mm = 0; mm < 252; mm++) {
            ull wp = pack2(__ldg(w2 + mm * 192 + o));
            const ulonglong2* sp = (const ulonglong2*)&sh1[mm * 8];
            ulonglong2 s0 = sp[0], s1 = sp[1];
            fma2(acc[0], s0.x, wp); fma2(acc[1], s0.y, wp);
            fma2(acc[2], s1.x, wp); fma2(acc[3], s1.y, wp);
        }
        float bb = b2[o];
        #pragma unroll
        for (int q = 0; q < 4; q++) {
            float2 r2 = unpack2(acc[q]);
            hout[(size_t)(m0 + q * 2) * 192 + o]     = r2.x + bb;
            hout[(size_t)(m0 + q * 2 + 1) * 192 + o] = r2.y + bb;
        }
    }
}

// ---------------- pooling (unchanged) ----------------
__global__ void pool_kernel(const float* __restrict__ h, float* __restrict__ pooled) {
    int b = blockIdx.x, cch = threadIdx.x;
    const float* hp = h + (size_t)b * NN * 192 + cch;
    float mx = -1e38f, mn = 1e38f;
    double sm = 0.0;
    #pragma unroll 4
    for (int n = 0; n < NN; n++) {
        float v = hp[(size_t)n * 192];
        mx = fmaxf(mx, v); mn = fminf(mn, v);
        sm += (double)v;
    }
    float smf = (float)sm;
    float* pb = pooled + b * 768;
    pb[cch]       = leakyf(mx);
    pb[192 + cch] = leakyf(mn);
    pb[384 + cch] = leakyf(smf);
    pb[576 + cch] = leakyf(__fmul_rn(smf, (1.0f / 256.0f)));
}

// ---------------- final head (unchanged) ----------------
__global__ void final_kernel(const float* __restrict__ pooled,
                             const float* __restrict__ w3, const float* __restrict__ b3,
                             const float* __restrict__ w4, const float* __restrict__ b4,
                             float* __restrict__ out) {
    __shared__ float sp[768];
    __shared__ float smid[96];
    int b = blockIdx.x, tid = threadIdx.x;
    for (int e = tid; e < 768; e += blockDim.x) sp[e] = pooled[b * 768 + e];
    __syncthreads();
    if (tid < 96) {
        float acc = 0.f;
        for (int k = 0; k < 768; k++) acc = fmaf(sp[k], w3[k * 96 + tid], acc);
        smid[tid] = leakyf(acc + b3[tid]);
    }
    __syncthreads();
    if (tid == 0) {
        float sacc = 0.f;
        for (int k = 0; k < 96; k++) sacc = fmaf(smid[k], w4[k], sacc);
        out[b] = sacc + b4[0];
    }
}

// ---------------- launch ----------------
extern "C" void kernel_launch(void* const* d_in, const int* in_sizes, int n_in,
                              void* d_out, int out_size) {
    const float* x = (const float*)d_in[0];
    const float* prm[24];
    for (int i = 0; i < 24; i++) prm[i] = (const float*)d_in[i + 1];

    float *ga, *gb, *gc, *gd, *gh, *gp;
    int* gi;
    cudaGetSymbolAddress((void**)&ga, g_a);
    cudaGetSymbolAddress((void**)&gb, g_b);
    cudaGetSymbolAddress((void**)&gc, g_c);
    cudaGetSymbolAddress((void**)&gd, g_d);
    cudaGetSymbolAddress((void**)&gh, g_h);
    cudaGetSymbolAddress((void**)&gp, g_pool);
    cudaGetSymbolAddress((void**)&gi, g_idx);

    knn_kernel<<<BB, NN>>>(x, 4, gi);
    edgeconv_kernel<4, 96><<<NPTS / 4, 512>>>(x, gi, prm[0], prm[1], prm[2], prm[3], ga);

    knn_kernel<<<BB, NN>>>(ga, 192, gi);
    edgeconv_kernel<192, 252><<<NPTS / 4, 512>>>(ga, gi, prm[4], prm[5], prm[6], prm[7], gb);

    knn_kernel<<<BB, NN>>>(gb, 192, gi);
    edgeconv_kernel<192, 252><<<NPTS / 4, 512>>>(gb, gi, prm[8], prm[9], prm[10], prm[11], gc);

    knn_kernel<<<BB, NN>>>(gc, 192, gi);
    edgeconv_kernel<192, 252><<<NPTS / 4, 512>>>(gc, gi, prm[12], prm[13], prm[14], prm[15], gd);

    nn12_kernel<<<NPTS / 8, 256>>>(x, ga, gb, gc, gd,
                                   prm[16], prm[17], prm[18], prm[19], gh);

    pool_kernel<<<BB, 192>>>(gh, gp);
    final_kernel<<<BB, 128>>>(gp, prm[20], prm[21], prm[22], prm[23], (float*)d_out);
}